// round 15
// baseline (speedup 1.0000x reference)
#include <cuda_runtime.h>
#include <cstdint>

// StateObsMLP via mma.sync tf32 + cp.async.bulk weight streaming.
// R15: W chunks move via TMA-engine bulk copies (16 x 2KB per chunk, issued
// by ONE thread, mbarrier completion) instead of 2048 per-thread cp.asyncs
// -> removes the MIO-issue bottleneck that pinned R10/R14 at ~31us.
// Pair-interleaved W layout (stride 520/pair): 2-way B-frag conflicts only.

#define CATS   32
#define EMB    256
#define B_MAX  2048
#define MT     16
#define KC     32
#define NTH    512
#define ASTR   36             // A smem row stride (cp.async path, padded)
#define XSTR   516            // x smem row stride
#define WPAIR  520            // floats per k-row-pair (512 + 8 pad)
#define WBUF   (16 * WPAIR)   // 8320 floats per W buffer
#define ABUF   (MT * ASTR)    // 576 floats
#define MAX_TILES (CATS + B_MAX / MT)
#define NCTAS  148

__device__ int g_perm[B_MAX];
__device__ int g_cat_start[CATS + 1];
__device__ int g_tiles[MAX_TILES];
__device__ int g_ntiles;

// ---------------------------------------------------------------------------
// Kernel 1: bin rows by category + flattened (cat, tile) worklist.
// ---------------------------------------------------------------------------
__global__ void bin_kernel(const int* __restrict__ cat, int B) {
    __shared__ int cnt[CATS];
    __shared__ int st[CATS + 1];
    __shared__ int cur[CATS];
    int t = threadIdx.x;
    if (t < CATS) cnt[t] = 0;
    __syncthreads();
    for (int b = t; b < B; b += blockDim.x) atomicAdd(&cnt[cat[b]], 1);
    __syncthreads();
    if (t == 0) {
        int s = 0;
        for (int c = 0; c < CATS; c++) { st[c] = s; s += cnt[c]; }
        st[CATS] = s;
        int n = 0;
        for (int c = 0; c < CATS; c++) {
            int nt = (cnt[c] + MT - 1) / MT;
            for (int i = 0; i < nt; i++) g_tiles[n++] = (c << 16) | i;
        }
        g_ntiles = n;
    }
    __syncthreads();
    if (t < CATS) cur[t] = st[t];
    __syncthreads();
    for (int b = t; b < B; b += blockDim.x) {
        int pos = atomicAdd(&cur[cat[b]], 1);
        g_perm[pos] = b;
    }
    if (t <= CATS) g_cat_start[t] = st[t];
}

// ---------------------------------------------------------------------------
// helpers
// ---------------------------------------------------------------------------
__device__ __forceinline__ uint32_t f2tf(float f) {
    uint32_t u;
    asm("cvt.rna.tf32.f32 %0, %1;" : "=r"(u) : "f"(f));
    return u;
}
__device__ __forceinline__ void mma_tf32(float* c,
    uint32_t a0, uint32_t a1, uint32_t a2, uint32_t a3,
    uint32_t b0, uint32_t b1)
{
    asm volatile(
        "mma.sync.aligned.m16n8k8.row.col.f32.tf32.tf32.f32 "
        "{%0,%1,%2,%3}, {%4,%5,%6,%7}, {%8,%9}, {%0,%1,%2,%3};"
        : "+f"(c[0]), "+f"(c[1]), "+f"(c[2]), "+f"(c[3])
        : "r"(a0), "r"(a1), "r"(a2), "r"(a3), "r"(b0), "r"(b1));
}
__device__ __forceinline__ uint32_t smem_u32(const void* p) {
    uint32_t a;
    asm("{ .reg .u64 t; cvta.to.shared.u64 t, %1; cvt.u32.u64 %0, t; }"
        : "=r"(a) : "l"(p));
    return a;
}
#define CP16(dst, src, sz) \
    asm volatile("cp.async.cg.shared.global [%0], [%1], 16, %2;" \
                 :: "r"(dst), "l"(src), "r"(sz))

// W smem index for element (k, n) in pair-interleaved layout.
__device__ __forceinline__ int widx(int k, int n) {
    return (k >> 1) * WPAIR + (k & 1) * 256 + n;
}

// One 32-K chunk: n=16 per warp (2 n-tiles), c[8].
template <bool CVTA>
__device__ __forceinline__ void chunk_mma(
    const float* __restrict__ Abase, int astride,
    const float* __restrict__ Wbuf,
    int gid, int tig, int nbase, float c[8])
{
    #pragma unroll
    for (int ks = 0; ks < 4; ks++) {
        int k0 = ks * 8;
        uint32_t a0, a1, a2, a3;
        if (CVTA) {
            a0 = f2tf(Abase[gid * astride + k0 + tig]);
            a1 = f2tf(Abase[(gid + 8) * astride + k0 + tig]);
            a2 = f2tf(Abase[gid * astride + k0 + tig + 4]);
            a3 = f2tf(Abase[(gid + 8) * astride + k0 + tig + 4]);
        } else {
            a0 = __float_as_uint(Abase[gid * astride + k0 + tig]);
            a1 = __float_as_uint(Abase[(gid + 8) * astride + k0 + tig]);
            a2 = __float_as_uint(Abase[gid * astride + k0 + tig + 4]);
            a3 = __float_as_uint(Abase[(gid + 8) * astride + k0 + tig + 4]);
        }
        #pragma unroll
        for (int nt = 0; nt < 2; nt++) {
            int nb = nbase + nt * 8;
            uint32_t b0 = f2tf(Wbuf[widx(k0 + tig,     nb + gid)]);
            uint32_t b1 = f2tf(Wbuf[widx(k0 + tig + 4, nb + gid)]);
            mma_tf32(c + nt * 4, a0, a1, a2, a3, b0, b1);
        }
    }
}

// ---------------------------------------------------------------------------
// Kernel 2: fused per (category, 16-row tile), 512 threads (16 warps,
// warp w -> n in [16w,16w+16)), persistent over worklist.
// smem floats: a_s 3*576=1728 | w_s 3*8320=24960 | x_s 16*516=8256
// total 34944 floats = 139776 B.
// ---------------------------------------------------------------------------
#define SMEM_FLOATS (3 * ABUF + 3 * WBUF + MT * XSTR)

__global__ __launch_bounds__(NTH, 1)
void fused_kernel(const float* __restrict__ state,
                  const float* __restrict__ obs,
                  const float* __restrict__ obs_W,
                  const float* __restrict__ obs_b,
                  const float* __restrict__ state_W,
                  const float* __restrict__ state_b,
                  const float* __restrict__ l2_W,
                  const float* __restrict__ l2_b,
                  float* __restrict__ out)
{
    extern __shared__ float sm[];
    float* a_s = sm;                 // 3 buffers of ABUF (cp.async, padded)
    float* w_s = a_s + 3 * ABUF;     // 3 buffers of WBUF (TMA bulk, pairs)
    float* x_s = w_s + 3 * WBUF;     // MT x XSTR (pre-rounded tf32 bits)
    __shared__ int rows_sh[MT];
    __shared__ __align__(8) unsigned long long mbar[3];

    int t    = threadIdx.x;
    int lane = t & 31;
    int wid  = t >> 5;
    int gid  = lane >> 2;
    int tig  = lane & 3;
    int nbase = wid * 16;

    uint32_t a_u = smem_u32(a_s);
    uint32_t w_u = smem_u32(w_s);
    uint32_t mb_u = smem_u32(&mbar[0]);

    if (t == 0) {
        #pragma unroll
        for (int i = 0; i < 3; i++)
            asm volatile("mbarrier.init.shared.b64 [%0], %1;"
                         :: "r"(mb_u + i * 8), "r"(1u) : "memory");
    }
    __syncthreads();

    uint32_t par = 0;   // parity bits for the 3 W mbarriers

    // Issue one W chunk: 16 bulk copies of 2KB (2 k-rows) by thread 0.
    #define W_ISSUE(Wp, ch, buf) do { \
        if (t == 0) { \
            uint32_t _mb = mb_u + (buf) * 8; \
            asm volatile("mbarrier.arrive.expect_tx.shared.b64 _, [%0], %1;" \
                         :: "r"(_mb), "r"(32768u) : "memory"); \
            const float* _src = (Wp) + (size_t)(ch) * KC * EMB; \
            uint32_t _db = w_u + (uint32_t)((buf) * WBUF) * 4; \
            _Pragma("unroll") \
            for (int p = 0; p < 16; p++) \
                asm volatile("cp.async.bulk.shared::cta.global" \
                    ".mbarrier::complete_tx::bytes [%0], [%1], %2, [%3];" \
                    :: "r"(_db + (uint32_t)(p * WPAIR) * 4), \
                       "l"(_src + p * 512), "r"(2048u), "r"(_mb) : "memory"); \
        } } while (0)

    // Wait for W chunk in `buf` (all threads), flip its parity.
    #define W_WAIT(buf) do { \
        uint32_t _mb = mb_u + (buf) * 8; \
        uint32_t _ph = (par >> (buf)) & 1u; \
        uint32_t _d; \
        asm volatile("{ .reg .pred p; " \
            "mbarrier.try_wait.parity.acquire.cta.shared::cta.b64 p, [%1], %2; " \
            "selp.b32 %0,1,0,p; }" : "=r"(_d) : "r"(_mb), "r"(_ph) : "memory"); \
        if (!_d) { \
            asm volatile("{ .reg .pred P1;\nWL%=: " \
                "mbarrier.try_wait.parity.acquire.cta.shared::cta.b64 P1, [%0], %1, 0x989680;\n" \
                "@P1 bra.uni WD%=;\nbra.uni WL%=;\nWD%=: }" \
                :: "r"(_mb), "r"(_ph) : "memory"); \
        } \
        par ^= (1u << (buf)); } while (0)

    #define COPY_A(Ap, lda, ch, buf) do { \
        if (t < 128) { \
            int row = t >> 3, q = t & 7; \
            int rg = rows_sh[row]; \
            const float* _src = (Ap) + (size_t)(rg < 0 ? 0 : rg) * (lda) \
                              + (ch) * KC + q * 4; \
            CP16(a_u + (uint32_t)((buf) * ABUF + row * ASTR + q * 4) * 4, \
                 _src, rg < 0 ? 0u : 16u); \
        } \
        asm volatile("cp.async.commit_group;"); } while (0)

    // Phase driver: 3 buffers, depth-2 prefetch, one barrier per chunk.
    #define PHASE(Ap, lda, HASA, Wp, nch, AV, astride, CVTA_) do { \
        if (HASA) COPY_A(Ap, lda, 0, 0); \
        W_ISSUE(Wp, 0, 0); \
        if ((nch) > 1) { \
            if (HASA) COPY_A(Ap, lda, 1, 1); \
            W_ISSUE(Wp, 1, 1); \
        } \
        for (int ch = 0; ch < (nch); ch++) { \
            W_WAIT(ch % 3); \
            if (HASA) { \
                if (ch + 1 < (nch)) asm volatile("cp.async.wait_group 1;"); \
                else                asm volatile("cp.async.wait_group 0;"); \
            } \
            __syncthreads(); \
            if (ch + 2 < (nch)) { \
                int nb3 = (ch + 2) % 3; \
                if (HASA) COPY_A(Ap, lda, ch + 2, nb3); \
                W_ISSUE(Wp, ch + 2, nb3); \
            } \
            chunk_mma<CVTA_>(AV(ch), astride, \
                             w_s + (ch % 3) * WBUF, gid, tig, nbase, c); \
        } } while (0)

    #define AV_GM(ch) (a_s + ((ch) % 3) * ABUF)
    #define AV_X(ch)  (x_s + (ch) * KC)

    int NT = g_ntiles;
    for (int widx_ = blockIdx.x; widx_ < NT; widx_ += gridDim.x) {
        __syncthreads();
        int ent  = g_tiles[widx_];
        int g    = ent >> 16;
        int tile = ent & 0xFFFF;
        int start = g_cat_start[g];
        int cnt   = g_cat_start[g + 1] - start;
        if (t < MT)
            rows_sh[t] = (tile * MT + t < cnt) ? g_perm[start + tile * MT + t] : -1;
        __syncthreads();

        float c[8];

        // --- Phase A: state_emb = relu(state @ state_W[g] + state_b[g]) ---
        #pragma unroll
        for (int i = 0; i < 8; i++) c[i] = 0.f;
        PHASE(state, 64, 1, state_W + (size_t)g * 64 * EMB, 2, AV_GM, ASTR, true);
        {
            const float* bs = state_b + (size_t)g * EMB;
            #pragma unroll
            for (int nt = 0; nt < 2; nt++) {
                int nb = nbase + nt * 8 + 2 * tig;
                float2 bb = *(const float2*)(bs + nb);
                float2 v0, v1;
                v0.x = __uint_as_float(f2tf(fmaxf(c[nt * 4 + 0] + bb.x, 0.f)));
                v0.y = __uint_as_float(f2tf(fmaxf(c[nt * 4 + 1] + bb.y, 0.f)));
                v1.x = __uint_as_float(f2tf(fmaxf(c[nt * 4 + 2] + bb.x, 0.f)));
                v1.y = __uint_as_float(f2tf(fmaxf(c[nt * 4 + 3] + bb.y, 0.f)));
                *(float2*)(x_s + gid * XSTR + nb)       = v0;
                *(float2*)(x_s + (gid + 8) * XSTR + nb) = v1;
            }
        }
        __syncthreads();

        // --- Phase B: obs_emb = obs @ obs_W + obs_b -> x cols [256,512) ---
        #pragma unroll
        for (int i = 0; i < 8; i++) c[i] = 0.f;
        PHASE(obs, 512, 1, obs_W, 16, AV_GM, ASTR, true);
        {
            #pragma unroll
            for (int nt = 0; nt < 2; nt++) {
                int nb = nbase + nt * 8 + 2 * tig;
                float2 bb = *(const float2*)(obs_b + nb);
                float2 v0, v1;
                v0.x = __uint_as_float(f2tf(c[nt * 4 + 0] + bb.x));
                v0.y = __uint_as_float(f2tf(c[nt * 4 + 1] + bb.y));
                v1.x = __uint_as_float(f2tf(c[nt * 4 + 2] + bb.x));
                v1.y = __uint_as_float(f2tf(c[nt * 4 + 3] + bb.y));
                *(float2*)(x_s + gid * XSTR + 256 + nb)       = v0;
                *(float2*)(x_s + (gid + 8) * XSTR + 256 + nb) = v1;
            }
        }
        __syncthreads();

        // --- Phase C: out = x @ l2_W[g] + l2_b[g], scatter rows ---
        #pragma unroll
        for (int i = 0; i < 8; i++) c[i] = 0.f;
        PHASE(state, 64, 0, l2_W + (size_t)g * 512 * EMB, 16, AV_X, XSTR, false);
        {
            const float* bl = l2_b + (size_t)g * EMB;
            int rg0 = rows_sh[gid];
            int rg1 = rows_sh[gid + 8];
            #pragma unroll
            for (int nt = 0; nt < 2; nt++) {
                int nb = nbase + nt * 8 + 2 * tig;
                float2 bb = *(const float2*)(bl + nb);
                if (rg0 >= 0) {
                    float2 v;
                    v.x = c[nt * 4 + 0] + bb.x;
                    v.y = c[nt * 4 + 1] + bb.y;
                    *(float2*)(out + (size_t)rg0 * EMB + nb) = v;
                }
                if (rg1 >= 0) {
                    float2 v;
                    v.x = c[nt * 4 + 2] + bb.x;
                    v.y = c[nt * 4 + 3] + bb.y;
                    *(float2*)(out + (size_t)rg1 * EMB + nb) = v;
                }
            }
        }
    }
}

// ---------------------------------------------------------------------------
extern "C" void kernel_launch(void* const* d_in, const int* in_sizes, int n_in,
                              void* d_out, int out_size) {
    const float* state   = (const float*)d_in[0];
    const float* obs     = (const float*)d_in[1];
    const int*   cat_ids = (const int*)  d_in[2];
    const float* obs_W   = (const float*)d_in[3];
    const float* obs_b   = (const float*)d_in[4];
    const float* state_W = (const float*)d_in[5];
    const float* state_b = (const float*)d_in[6];
    const float* l2_W    = (const float*)d_in[7];
    const float* l2_b    = (const float*)d_in[8];
    float* out = (float*)d_out;

    int B = in_sizes[2];

    size_t smem_bytes = SMEM_FLOATS * sizeof(float);   // 139776
    cudaFuncSetAttribute(fused_kernel,
                         cudaFuncAttributeMaxDynamicSharedMemorySize,
                         (int)smem_bytes);

    bin_kernel<<<1, 1024>>>(cat_ids, B);
    fused_kernel<<<NCTAS, NTH, smem_bytes>>>(
        state, obs, obs_W, obs_b, state_W, state_b, l2_W, l2_b, out);
}

// round 16
// speedup vs baseline: 1.1698x; 1.1698x over previous
#include <cuda_runtime.h>
#include <cstdint>

// StateObsMLP via mma.sync tf32 (baseline PTX, compute_103-safe).
// R16: BARRIER-FREE mainloops. Each warp owns a private 3-deep ring of
// 32k x 16n weight slices (stride 24, conflict-free), synced with
// cp.async.wait_group + __syncwarp only. A-tiles loaded once per tile.
// ~3 __syncthreads per tile (was ~36) -> removes the per-chunk CTA-wide
// sync cost that pinned R10/R14/R15 at ~31-34us.

#define CATS   32
#define EMB    256
#define B_MAX  2048
#define MT     16
#define KC     32
#define NTH    512
#define SASTR  68              // state A row stride (4*gid+tig banks unique)
#define OASTR  516             // obs A / x row stride (4*gid+tig unique)
#define WROW   24              // W slice k-row stride (24*tig+gid unique)
#define WBUFW  (KC * WROW)     // 768 floats per W buffer
#define WPW    (3 * WBUFW)     // 2304 floats per warp
#define MAX_TILES (CATS + B_MAX / MT)
#define NCTAS  148

__device__ int g_perm[B_MAX];
__device__ int g_cat_start[CATS + 1];
__device__ int g_tiles[MAX_TILES];
__device__ int g_ntiles;

// ---------------------------------------------------------------------------
// Kernel 1: bin rows by category + flattened (cat, tile) worklist.
// ---------------------------------------------------------------------------
__global__ void bin_kernel(const int* __restrict__ cat, int B) {
    __shared__ int cnt[CATS];
    __shared__ int st[CATS + 1];
    __shared__ int cur[CATS];
    int t = threadIdx.x;
    if (t < CATS) cnt[t] = 0;
    __syncthreads();
    for (int b = t; b < B; b += blockDim.x) atomicAdd(&cnt[cat[b]], 1);
    __syncthreads();
    if (t == 0) {
        int s = 0;
        for (int c = 0; c < CATS; c++) { st[c] = s; s += cnt[c]; }
        st[CATS] = s;
        int n = 0;
        for (int c = 0; c < CATS; c++) {
            int nt = (cnt[c] + MT - 1) / MT;
            for (int i = 0; i < nt; i++) g_tiles[n++] = (c << 16) | i;
        }
        g_ntiles = n;
    }
    __syncthreads();
    if (t < CATS) cur[t] = st[t];
    __syncthreads();
    for (int b = t; b < B; b += blockDim.x) {
        int pos = atomicAdd(&cur[cat[b]], 1);
        g_perm[pos] = b;
    }
    if (t <= CATS) g_cat_start[t] = st[t];
}

// ---------------------------------------------------------------------------
// helpers
// ---------------------------------------------------------------------------
__device__ __forceinline__ uint32_t f2tf(float f) {
    uint32_t u;
    asm("cvt.rna.tf32.f32 %0, %1;" : "=r"(u) : "f"(f));
    return u;
}
__device__ __forceinline__ void mma_tf32(float* c,
    uint32_t a0, uint32_t a1, uint32_t a2, uint32_t a3,
    uint32_t b0, uint32_t b1)
{
    asm volatile(
        "mma.sync.aligned.m16n8k8.row.col.f32.tf32.tf32.f32 "
        "{%0,%1,%2,%3}, {%4,%5,%6,%7}, {%8,%9}, {%0,%1,%2,%3};"
        : "+f"(c[0]), "+f"(c[1]), "+f"(c[2]), "+f"(c[3])
        : "r"(a0), "r"(a1), "r"(a2), "r"(a3), "r"(b0), "r"(b1));
}
__device__ __forceinline__ uint32_t smem_u32(const void* p) {
    uint32_t a;
    asm("{ .reg .u64 t; cvta.to.shared.u64 t, %1; cvt.u32.u64 %0, t; }"
        : "=r"(a) : "l"(p));
    return a;
}
#define CP16(dst, src, sz) \
    asm volatile("cp.async.cg.shared.global [%0], [%1], 16, %2;" \
                 :: "r"(dst), "l"(src), "r"(sz))

// One 32-K chunk: n=16 per warp (2 n-tiles), c[8], warp-private W slice.
// B frag banks: (24*tig + 8*nt + gid) mod 32 -> {0,24,16,8}+gid: unique.
template <bool CVTA>
__device__ __forceinline__ void chunk_mma(
    const float* __restrict__ Abase, int astride,
    const float* __restrict__ Wbuf,
    int gid, int tig, float c[8])
{
    #pragma unroll
    for (int ks = 0; ks < 4; ks++) {
        int k0 = ks * 8;
        uint32_t a0, a1, a2, a3;
        if (CVTA) {
            a0 = f2tf(Abase[gid * astride + k0 + tig]);
            a1 = f2tf(Abase[(gid + 8) * astride + k0 + tig]);
            a2 = f2tf(Abase[gid * astride + k0 + tig + 4]);
            a3 = f2tf(Abase[(gid + 8) * astride + k0 + tig + 4]);
        } else {
            a0 = __float_as_uint(Abase[gid * astride + k0 + tig]);
            a1 = __float_as_uint(Abase[(gid + 8) * astride + k0 + tig]);
            a2 = __float_as_uint(Abase[gid * astride + k0 + tig + 4]);
            a3 = __float_as_uint(Abase[(gid + 8) * astride + k0 + tig + 4]);
        }
        #pragma unroll
        for (int nt = 0; nt < 2; nt++) {
            uint32_t b0 = f2tf(Wbuf[(k0 + tig) * WROW + nt * 8 + gid]);
            uint32_t b1 = f2tf(Wbuf[(k0 + tig + 4) * WROW + nt * 8 + gid]);
            mma_tf32(c + nt * 4, a0, a1, a2, a3, b0, b1);
        }
    }
}

// ---------------------------------------------------------------------------
// Kernel 2: fused per (category, 16-row tile), 512 threads (16 warps,
// warp w -> n in [16w,16w+16)), persistent over worklist.
// smem floats: s_a 16*68=1088 | a_o 16*516=8256 | x_s 16*516=8256 |
//              w_s 16*2304=36864   total 54464 fl = 217856 B (1 CTA/SM).
// ---------------------------------------------------------------------------
#define SMEM_FLOATS (MT * SASTR + MT * OASTR + MT * OASTR + 16 * WPW)

__global__ __launch_bounds__(NTH, 1)
void fused_kernel(const float* __restrict__ state,
                  const float* __restrict__ obs,
                  const float* __restrict__ obs_W,
                  const float* __restrict__ obs_b,
                  const float* __restrict__ state_W,
                  const float* __restrict__ state_b,
                  const float* __restrict__ l2_W,
                  const float* __restrict__ l2_b,
                  float* __restrict__ out)
{
    extern __shared__ float sm[];
    float* s_a = sm;                    // state A tile 16 x 68
    float* a_o = s_a + MT * SASTR;      // obs A tile 16 x 516
    float* x_s = a_o + MT * OASTR;      // concat x 16 x 516 (tf32-rounded)
    float* w_s = x_s + MT * OASTR;      // 16 warps x 3 x 768
    __shared__ int rows_sh[MT];

    int t    = threadIdx.x;
    int lane = t & 31;
    int wid  = t >> 5;
    int gid  = lane >> 2;       // m16 row group / B n index
    int tig  = lane & 3;        // k index within frag
    int nbase = wid * 16;       // warp's n range [nbase, nbase+16)

    uint32_t sa_u = smem_u32(s_a);
    uint32_t ao_u = smem_u32(a_o);
    uint32_t w_u  = smem_u32(w_s);
    float* w_warp = w_s + wid * WPW;

    int NT = g_ntiles;
    for (int widx = blockIdx.x; widx < NT; widx += gridDim.x) {
        __syncthreads();            // all warps done with prev tile's smem
        int ent  = g_tiles[widx];
        int g    = ent >> 16;
        int tile = ent & 0xFFFF;
        int start = g_cat_start[g];
        int cnt   = g_cat_start[g + 1] - start;
        if (t < MT)
            rows_sh[t] = (tile * MT + t < cnt) ? g_perm[start + tile * MT + t] : -1;
        __syncthreads();

        // ---- load BOTH A tiles once (state 16x64, obs 16x512) ----
        if (t < 256) {
            int row = t >> 4, q = t & 15;
            int rg = rows_sh[row];
            CP16(sa_u + (uint32_t)(row * SASTR + q * 4) * 4,
                 state + (size_t)(rg < 0 ? 0 : rg) * 64 + q * 4,
                 rg < 0 ? 0u : 16u);
        }
        #pragma unroll
        for (int j = 0; j < 4; j++) {
            int idx = j * NTH + t;
            int row = idx >> 7, q = idx & 127;
            int rg = rows_sh[row];
            CP16(ao_u + (uint32_t)(row * OASTR + q * 4) * 4,
                 obs + (size_t)(rg < 0 ? 0 : rg) * 512 + q * 4,
                 rg < 0 ? 0u : 16u);
        }
        asm volatile("cp.async.commit_group;");
        asm volatile("cp.async.wait_group 0;");
        __syncthreads();            // A tiles visible to all warps

        float c[8];

        // Per-warp W slice copy: 32 k-rows x 16 cols of chunk `ch`.
        #define W_COPY(Wp, ch, buf) do { \
            const float* _src = (Wp) + (size_t)(ch) * KC * EMB + nbase; \
            uint32_t _dst = w_u + (uint32_t)(wid * WPW + (buf) * WBUFW) * 4; \
            _Pragma("unroll") \
            for (int j = 0; j < 4; j++) { \
                int idx = j * 32 + lane; \
                int k = idx >> 2, q = idx & 3; \
                CP16(_dst + (uint32_t)(k * WROW + q * 4) * 4, \
                     _src + k * EMB + q * 4, 16); \
            } \
            asm volatile("cp.async.commit_group;"); } while (0)

        // Barrier-free mainloop: 3-deep warp-private ring, depth-2 prefetch.
        #define WPHASE(Wp, nch, AV, astride, CVTA_) do { \
            W_COPY(Wp, 0, 0); \
            if ((nch) > 1) W_COPY(Wp, 1, 1); \
            for (int ch = 0; ch < (nch); ch++) { \
                if (ch + 1 < (nch)) asm volatile("cp.async.wait_group 1;"); \
                else                asm volatile("cp.async.wait_group 0;"); \
                __syncwarp(); \
                if (ch + 2 < (nch)) W_COPY(Wp, ch + 2, (ch + 2) % 3); \
                chunk_mma<CVTA_>(AV(ch), astride, \
                                 w_warp + (ch % 3) * WBUFW, gid, tig, c); \
            } } while (0)

        #define AV_S(ch) (s_a + (ch) * KC)
        #define AV_O(ch) (a_o + (ch) * KC)
        #define AV_X(ch) (x_s + (ch) * KC)

        // --- Phase A: state_emb = relu(state @ state_W[g] + state_b[g]) ---
        #pragma unroll
        for (int i = 0; i < 8; i++) c[i] = 0.f;
        WPHASE(state_W + (size_t)g * 64 * EMB, 2, AV_S, SASTR, true);
        {
            const float* bs = state_b + (size_t)g * EMB;
            #pragma unroll
            for (int nt = 0; nt < 2; nt++) {
                int nb = nbase + nt * 8 + 2 * tig;
                float2 bb = *(const float2*)(bs + nb);
                float2 v0, v1;
                v0.x = __uint_as_float(f2tf(fmaxf(c[nt * 4 + 0] + bb.x, 0.f)));
                v0.y = __uint_as_float(f2tf(fmaxf(c[nt * 4 + 1] + bb.y, 0.f)));
                v1.x = __uint_as_float(f2tf(fmaxf(c[nt * 4 + 2] + bb.x, 0.f)));
                v1.y = __uint_as_float(f2tf(fmaxf(c[nt * 4 + 3] + bb.y, 0.f)));
                *(float2*)(x_s + gid * OASTR + nb)       = v0;
                *(float2*)(x_s + (gid + 8) * OASTR + nb) = v1;
            }
        }
        // no barrier: phase B touches neither x_s nor s_a

        // --- Phase B: obs_emb = obs @ obs_W + obs_b -> x cols [256,512) ---
        #pragma unroll
        for (int i = 0; i < 8; i++) c[i] = 0.f;
        WPHASE(obs_W, 16, AV_O, OASTR, true);
        {
            #pragma unroll
            for (int nt = 0; nt < 2; nt++) {
                int nb = nbase + nt * 8 + 2 * tig;
                float2 bb = *(const float2*)(obs_b + nb);
                float2 v0, v1;
                v0.x = __uint_as_float(f2tf(c[nt * 4 + 0] + bb.x));
                v0.y = __uint_as_float(f2tf(c[nt * 4 + 1] + bb.y));
                v1.x = __uint_as_float(f2tf(c[nt * 4 + 2] + bb.x));
                v1.y = __uint_as_float(f2tf(c[nt * 4 + 3] + bb.y));
                *(float2*)(x_s + gid * OASTR + 256 + nb)       = v0;
                *(float2*)(x_s + (gid + 8) * OASTR + 256 + nb) = v1;
            }
        }
        __syncthreads();            // x complete; all warps may read all of x

        // --- Phase C: out = x @ l2_W[g] + l2_b[g], scatter rows ---
        #pragma unroll
        for (int i = 0; i < 8; i++) c[i] = 0.f;
        WPHASE(l2_W + (size_t)g * 512 * EMB, 16, AV_X, OASTR, false);
        {
            const float* bl = l2_b + (size_t)g * EMB;
            int rg0 = rows_sh[gid];
            int rg1 = rows_sh[gid + 8];
            #pragma unroll
            for (int nt = 0; nt < 2; nt++) {
                int nb = nbase + nt * 8 + 2 * tig;
                float2 bb = *(const float2*)(bl + nb);
                if (rg0 >= 0) {
                    float2 v;
                    v.x = c[nt * 4 + 0] + bb.x;
                    v.y = c[nt * 4 + 1] + bb.y;
                    *(float2*)(out + (size_t)rg0 * EMB + nb) = v;
                }
                if (rg1 >= 0) {
                    float2 v;
                    v.x = c[nt * 4 + 2] + bb.x;
                    v.y = c[nt * 4 + 3] + bb.y;
                    *(float2*)(out + (size_t)rg1 * EMB + nb) = v;
                }
            }
        }
    }
}

// ---------------------------------------------------------------------------
extern "C" void kernel_launch(void* const* d_in, const int* in_sizes, int n_in,
                              void* d_out, int out_size) {
    const float* state   = (const float*)d_in[0];
    const float* obs     = (const float*)d_in[1];
    const int*   cat_ids = (const int*)  d_in[2];
    const float* obs_W   = (const float*)d_in[3];
    const float* obs_b   = (const float*)d_in[4];
    const float* state_W = (const float*)d_in[5];
    const float* state_b = (const float*)d_in[6];
    const float* l2_W    = (const float*)d_in[7];
    const float* l2_b    = (const float*)d_in[8];
    float* out = (float*)d_out;

    int B = in_sizes[2];

    size_t smem_bytes = SMEM_FLOATS * sizeof(float);   // 217856
    cudaFuncSetAttribute(fused_kernel,
                         cudaFuncAttributeMaxDynamicSharedMemorySize,
                         (int)smem_bytes);

    bin_kernel<<<1, 1024>>>(cat_ids, B);
    fused_kernel<<<NCTAS, NTH, smem_bytes>>>(
        state, obs, obs_W, obs_b, state_W, state_b, l2_W, l2_b, out);
}

// round 17
// speedup vs baseline: 1.6372x; 1.3995x over previous
#include <cuda_runtime.h>
#include <cuda_fp16.h>
#include <cstdint>

// StateObsMLP via mma.sync m16n8k16 fp16 (baseline PTX, compute_103-safe).
// R17: fp16 MMA (same 10-bit mantissa as tf32) with k-pair-packed half2
// operands everywhere -> 4 MMAs + 16 LDS per warp-chunk, ZERO in-loop cvts,
// halved weight traffic. Prep kernel (merged with binning) packs weights
// once; A tiles packed per-tile; x written packed at epilogues.
// Keeps R16's barrier-free warp-private W rings.

#define CATS   32
#define EMB    256
#define B_MAX  2048
#define MT     16
#define NTH    512
#define SASTRW 36              // state_p word stride (32+4)
#define OASTRW 260             // obs_p / x_p word stride (256+4)
#define WROWW  24              // W slice k2-row stride in words (16+8)
#define WBUFW  (16 * WROWW)    // 384 words per W slice buffer
#define WPW    (3 * WBUFW)     // 1152 words per warp
#define MAX_TILES (CATS + B_MAX / MT)
#define NCTAS  148

__device__ int g_perm[B_MAX];
__device__ int g_cat_start[CATS + 1];
__device__ int g_tiles[MAX_TILES];
__device__ int g_ntiles;

// Packed half2 weights: word (k2, n) = {W[2k2][n] lo, W[2k2+1][n] hi}
__device__ uint32_t g_obsWp[256 * 256];          // 512/2 k2-rows x 256
__device__ uint32_t g_stateWp[CATS * 32 * 256];  // per cat: 32 k2 x 256
__device__ uint32_t g_l2Wp[CATS * 256 * 256];    // per cat: 256 k2 x 256

__device__ __forceinline__ uint32_t pack2(float lo, float hi) {
    __half2 h = __floats2half2_rn(lo, hi);
    return *reinterpret_cast<uint32_t*>(&h);
}
__device__ __forceinline__ uint32_t smem_u32(const void* p) {
    uint32_t a;
    asm("{ .reg .u64 t; cvta.to.shared.u64 t, %1; cvt.u32.u64 %0, t; }"
        : "=r"(a) : "l"(p));
    return a;
}
__device__ __forceinline__ void mma_f16(float* c,
    uint32_t a0, uint32_t a1, uint32_t a2, uint32_t a3,
    uint32_t b0, uint32_t b1)
{
    asm volatile(
        "mma.sync.aligned.m16n8k16.row.col.f32.f16.f16.f32 "
        "{%0,%1,%2,%3}, {%4,%5,%6,%7}, {%8,%9}, {%0,%1,%2,%3};"
        : "+f"(c[0]), "+f"(c[1]), "+f"(c[2]), "+f"(c[3])
        : "r"(a0), "r"(a1), "r"(a2), "r"(a3), "r"(b0), "r"(b1));
}
#define CP16(dst, src) \
    asm volatile("cp.async.cg.shared.global [%0], [%1], 16;" \
                 :: "r"(dst), "l"(src))

// ---------------------------------------------------------------------------
// Kernel 1 (prep): block 0 bins rows by category + builds worklist;
// blocks 1..N pack all weights fp32 -> half2 k-pair words.
// ---------------------------------------------------------------------------
__global__ void prep_kernel(const int* __restrict__ cat, int B,
                            const float4* __restrict__ obs_W,
                            const float4* __restrict__ state_W,
                            const float4* __restrict__ l2_W)
{
    if (blockIdx.x == 0) {
        __shared__ int cnt[CATS];
        __shared__ int st[CATS + 1];
        __shared__ int cur[CATS];
        int t = threadIdx.x;
        if (t < CATS) cnt[t] = 0;
        __syncthreads();
        for (int b = t; b < B; b += blockDim.x) atomicAdd(&cnt[cat[b]], 1);
        __syncthreads();
        if (t == 0) {
            int s = 0;
            for (int c = 0; c < CATS; c++) { st[c] = s; s += cnt[c]; }
            st[CATS] = s;
            int n = 0;
            for (int c = 0; c < CATS; c++) {
                int nt = (cnt[c] + MT - 1) / MT;
                for (int i = 0; i < nt; i++) g_tiles[n++] = (c << 16) | i;
            }
            g_ntiles = n;
        }
        __syncthreads();
        if (t < CATS) cur[t] = st[t];
        __syncthreads();
        for (int b = t; b < B; b += blockDim.x) {
            int pos = atomicAdd(&cur[cat[b]], 1);
            g_perm[pos] = b;
        }
        if (t <= CATS) g_cat_start[t] = st[t];
        return;
    }
    // weight packing: task = one uint4 (4 output words = 4 n, one k2 row)
    const int NO4 = 256 * 256 / 4;        // 16384
    const int NS4 = CATS * 32 * 256 / 4;  // 65536
    const int NL4 = CATS * 256 * 256 / 4; // 524288
    int j = (blockIdx.x - 1) * blockDim.x + threadIdx.x;
    if (j >= NO4 + NS4 + NL4) return;
    const float4* src; uint4* dst; int l;
    if (j < NO4)             { src = obs_W;   dst = (uint4*)g_obsWp;   l = j; }
    else if (j < NO4 + NS4)  { src = state_W; dst = (uint4*)g_stateWp; l = j - NO4; }
    else                     { src = l2_W;    dst = (uint4*)g_l2Wp;    l = j - NO4 - NS4; }
    int k2 = l >> 6, n4 = l & 63;
    float4 e = src[(size_t)(2 * k2) * 64 + n4];      // even k row
    float4 o = src[(size_t)(2 * k2 + 1) * 64 + n4];  // odd k row
    uint4 w;
    w.x = pack2(e.x, o.x);
    w.y = pack2(e.y, o.y);
    w.z = pack2(e.z, o.z);
    w.w = pack2(e.w, o.w);
    dst[l] = w;
}

// ---------------------------------------------------------------------------
// One k32 chunk, n=16 per warp: 8 A-LDS + 8 B-LDS + 4 MMA, no cvts.
// Ab: packed A words (16 k2 words per chunk), Wb: warp-private slice buffer.
// ---------------------------------------------------------------------------
__device__ __forceinline__ void chunk_mma16(
    const uint32_t* __restrict__ Ab, int astrw,
    const uint32_t* __restrict__ Wb,
    int gid, int tig, float c[8])
{
    #pragma unroll
    for (int ks = 0; ks < 2; ks++) {
        int r = ks * 8 + tig;
        uint32_t a0 = Ab[gid * astrw + r];
        uint32_t a1 = Ab[(gid + 8) * astrw + r];
        uint32_t a2 = Ab[gid * astrw + r + 4];
        uint32_t a3 = Ab[(gid + 8) * astrw + r + 4];
        #pragma unroll
        for (int nt = 0; nt < 2; nt++) {
            uint32_t b0 = Wb[r * WROWW + nt * 8 + gid];
            uint32_t b1 = Wb[(r + 4) * WROWW + nt * 8 + gid];
            mma_f16(c + nt * 4, a0, a1, a2, a3, b0, b1);
        }
    }
}

// ---------------------------------------------------------------------------
// Kernel 2: fused per (category, 16-row tile), 512 threads (16 warps,
// warp w -> n in [16w,16w+16)), persistent over worklist.
// smem words: sp 576 | op 4160 | xp 4160 | w 16*1152=18432 = 27328 w = 107KB
// ---------------------------------------------------------------------------
#define SMEM_WORDS (MT * SASTRW + 2 * MT * OASTRW + 16 * WPW)

__global__ __launch_bounds__(NTH, 1)
void fused_kernel(const float* __restrict__ state,
                  const float* __restrict__ obs,
                  const float* __restrict__ obs_b,
                  const float* __restrict__ state_b,
                  const float* __restrict__ l2_b,
                  float* __restrict__ out)
{
    extern __shared__ uint32_t smw[];
    uint32_t* sp = smw;                      // state_p 16 x 36
    uint32_t* op = sp + MT * SASTRW;         // obs_p 16 x 260
    uint32_t* xp = op + MT * OASTRW;         // x_p 16 x 260
    uint32_t* ws = xp + MT * OASTRW;         // 16 warps x 3 x 384
    __shared__ int rows_sh[MT];

    int t    = threadIdx.x;
    int lane = t & 31;
    int wid  = t >> 5;
    int gid  = lane >> 2;       // m16 row group / B n index
    int tig  = lane & 3;        // k index within frag
    int nbase = wid * 16;       // warp's n range [nbase, nbase+16)

    uint32_t ws_u = smem_u32(ws);
    uint32_t* w_warp = ws + wid * WPW;

    int NT = g_ntiles;
    for (int widx = blockIdx.x; widx < NT; widx += gridDim.x) {
        __syncthreads();
        int ent  = g_tiles[widx];
        int g    = ent >> 16;
        int tile = ent & 0xFFFF;
        int start = g_cat_start[g];
        int cnt   = g_cat_start[g + 1] - start;
        if (t < MT)
            rows_sh[t] = (tile * MT + t < cnt) ? g_perm[start + tile * MT + t] : -1;
        __syncthreads();

        // ---- pack A tiles into half2 words (once per tile) ----
        if (t < 512) {
            int row = t >> 5, k2 = t & 31;
            int rg = rows_sh[row];
            float2 v = make_float2(0.f, 0.f);
            if (rg >= 0) v = *(const float2*)(state + (size_t)rg * 64 + 2 * k2);
            sp[row * SASTRW + k2] = pack2(v.x, v.y);
        }
        #pragma unroll
        for (int j = 0; j < 8; j++) {
            int idx = j * NTH + t;
            int row = idx >> 8, k2 = idx & 255;
            int rg = rows_sh[row];
            float2 v = make_float2(0.f, 0.f);
            if (rg >= 0) v = *(const float2*)(obs + (size_t)rg * 512 + 2 * k2);
            op[row * OASTRW + k2] = pack2(v.x, v.y);
        }
        __syncthreads();

        float c[8];

        // Per-warp W slice copy: 16 k2-rows x 16 n-words of chunk `ch`.
        #define W_COPY(Wp_, ch, buf) do { \
            const uint32_t* _src = (Wp_) + (size_t)(ch) * 16 * 256 + nbase; \
            uint32_t _dst = ws_u + (uint32_t)(wid * WPW + (buf) * WBUFW) * 4; \
            _Pragma("unroll") \
            for (int jj = 0; jj < 2; jj++) { \
                int idx = jj * 32 + lane; \
                int r = idx >> 2, q = idx & 3; \
                CP16(_dst + (uint32_t)(r * WROWW + q * 4) * 4, \
                     _src + (size_t)r * 256 + q * 4); \
            } \
            asm volatile("cp.async.commit_group;"); } while (0)

        // Barrier-free mainloop: 3-deep warp-private ring, depth-2 prefetch.
        #define WPHASE(Wp_, nch, AV, astrw) do { \
            W_COPY(Wp_, 0, 0); \
            if ((nch) > 1) W_COPY(Wp_, 1, 1); \
            for (int ch = 0; ch < (nch); ch++) { \
                if (ch + 1 < (nch)) asm volatile("cp.async.wait_group 1;"); \
                else                asm volatile("cp.async.wait_group 0;"); \
                __syncwarp(); \
                if (ch + 2 < (nch)) W_COPY(Wp_, ch + 2, (ch + 2) % 3); \
                chunk_mma16(AV(ch), astrw, \
                            w_warp + (ch % 3) * WBUFW, gid, tig, c); \
            } } while (0)

        #define AV_S(ch) (sp + (ch) * 16)
        #define AV_O(ch) (op + (ch) * 16)
        #define AV_X(ch) (xp + (ch) * 16)

        // --- Phase A: state_emb = relu(state @ state_W[g] + state_b[g]) ---
        #pragma unroll
        for (int i = 0; i < 8; i++) c[i] = 0.f;
        WPHASE(g_stateWp + (size_t)g * 32 * 256, 2, AV_S, SASTRW);
        {
            const float* bs = state_b + (size_t)g * EMB;
            #pragma unroll
            for (int nt = 0; nt < 2; nt++) {
                int nb = nbase + nt * 8 + 2 * tig;
                float2 bb = *(const float2*)(bs + nb);
                int wcol = (nbase >> 1) + nt * 4 + tig;
                xp[gid * OASTRW + wcol] =
                    pack2(fmaxf(c[nt * 4 + 0] + bb.x, 0.f),
                          fmaxf(c[nt * 4 + 1] + bb.y, 0.f));
                xp[(gid + 8) * OASTRW + wcol] =
                    pack2(fmaxf(c[nt * 4 + 2] + bb.x, 0.f),
                          fmaxf(c[nt * 4 + 3] + bb.y, 0.f));
            }
        }
        // no barrier: phase B touches neither xp nor sp

        // --- Phase B: obs_emb = obs @ obs_W + obs_b -> x words [128,256) ---
        #pragma unroll
        for (int i = 0; i < 8; i++) c[i] = 0.f;
        WPHASE(g_obsWp, 16, AV_O, OASTRW);
        {
            #pragma unroll
            for (int nt = 0; nt < 2; nt++) {
                int nb = nbase + nt * 8 + 2 * tig;
                float2 bb = *(const float2*)(obs_b + nb);
                int wcol = 128 + (nbase >> 1) + nt * 4 + tig;
                xp[gid * OASTRW + wcol] =
                    pack2(c[nt * 4 + 0] + bb.x, c[nt * 4 + 1] + bb.y);
                xp[(gid + 8) * OASTRW + wcol] =
                    pack2(c[nt * 4 + 2] + bb.x, c[nt * 4 + 3] + bb.y);
            }
        }
        __syncthreads();   // x complete; all warps read all of x in phase C

        // --- Phase C: out = x @ l2_W[g] + l2_b[g], scatter rows ---
        #pragma unroll
        for (int i = 0; i < 8; i++) c[i] = 0.f;
        WPHASE(g_l2Wp + (size_t)g * 256 * 256, 16, AV_X, OASTRW);
        {
            const float* bl = l2_b + (size_t)g * EMB;
            int rg0 = rows_sh[gid];
            int rg1 = rows_sh[gid + 8];
            #pragma unroll
            for (int nt = 0; nt < 2; nt++) {
                int nb = nbase + nt * 8 + 2 * tig;
                float2 bb = *(const float2*)(bl + nb);
                if (rg0 >= 0) {
                    float2 v;
                    v.x = c[nt * 4 + 0] + bb.x;
                    v.y = c[nt * 4 + 1] + bb.y;
                    *(float2*)(out + (size_t)rg0 * EMB + nb) = v;
                }
                if (rg1 >= 0) {
                    float2 v;
                    v.x = c[nt * 4 + 2] + bb.x;
                    v.y = c[nt * 4 + 3] + bb.y;
                    *(float2*)(out + (size_t)rg1 * EMB + nb) = v;
                }
            }
        }
    }
}

// ---------------------------------------------------------------------------
extern "C" void kernel_launch(void* const* d_in, const int* in_sizes, int n_in,
                              void* d_out, int out_size) {
    const float* state   = (const float*)d_in[0];
    const float* obs     = (const float*)d_in[1];
    const int*   cat_ids = (const int*)  d_in[2];
    const float* obs_W   = (const float*)d_in[3];
    const float* obs_b   = (const float*)d_in[4];
    const float* state_W = (const float*)d_in[5];
    const float* state_b = (const float*)d_in[6];
    const float* l2_W    = (const float*)d_in[7];
    const float* l2_b    = (const float*)d_in[8];
    float* out = (float*)d_out;

    int B = in_sizes[2];

    size_t smem_bytes = SMEM_WORDS * sizeof(uint32_t);   // 109312
    cudaFuncSetAttribute(fused_kernel,
                         cudaFuncAttributeMaxDynamicSharedMemorySize,
                         (int)smem_bytes);

    // prep: block 0 = binning; blocks 1..1185 = weight packing (606208 tasks)
    prep_kernel<<<1186, 512>>>(cat_ids, B, (const float4*)obs_W,
                               (const float4*)state_W, (const float4*)l2_W);
    fused_kernel<<<NCTAS, NTH, smem_bytes>>>(
        state, obs, obs_b, state_b, l2_b, out);
}